// round 1
// baseline (speedup 1.0000x reference)
#include <cuda_runtime.h>

// Permutation: x[B=16, C=64, H=256, W=256] fp32
//   -> reshape (B, s0=2, c=32, s1=16, h=16, s2=16, w=16)
//   -> transpose (0,1,3,5,2,4,6) => out[B, s0, s1, s2, c, h, w]
//
// out[b][i][j][k][cc][hh][ww] = x[b][i*32+cc][j*16+hh][k*16+ww]
//
// Innermost w=16 floats (64B) contiguous in both tensors -> float4 copy,
// output-linear indexing: fully coalesced stores, 64B-segment loads.

static constexpr unsigned TOTAL_F4 = (16u * 64u * 256u * 256u) / 4u;  // 16,777,216

__global__ __launch_bounds__(256)
void reshape_78271484002964_kernel(const float4* __restrict__ in,
                                   float4* __restrict__ out) {
    unsigned t = blockIdx.x * blockDim.x + threadIdx.x;  // float4 index in output

    // Decompose output float4 index:
    // out float idx = (((((b*2+i)*16+j)*16+k)*32+cc)*16+hh)*16+ww
    // in float4 units (w=16 floats = 4 float4s): ww4 = ww/4
    unsigned ww4 = t & 3u;         // float4 within w-chunk
    unsigned r   = t >> 2;
    unsigned hh  = r & 15u;  r >>= 4;
    unsigned cc  = r & 31u;  r >>= 5;
    unsigned k   = r & 15u;  r >>= 4;
    unsigned j   = r & 15u;  r >>= 4;
    unsigned i   = r & 1u;
    unsigned b   = r >> 1;

    // Input: channel = b*64 + i*32 + cc; row = j*16 + hh; col4 = k*4 + ww4
    // in float4 idx = channel*(256*256/4) + row*(256/4) + col4
    //              = (channel << 14) + (row << 6) + (k << 2) + ww4
    unsigned channel = (b << 6) + (i << 5) + cc;
    unsigned row     = (j << 4) + hh;
    unsigned in_f4   = (channel << 14) + (row << 6) + (k << 2) + ww4;

    out[t] = __ldg(&in[in_f4]);
}

extern "C" void kernel_launch(void* const* d_in, const int* in_sizes, int n_in,
                              void* d_out, int out_size) {
    const float4* in  = (const float4*)d_in[0];
    float4*       out = (float4*)d_out;

    dim3 block(256);
    dim3 grid(TOTAL_F4 / 256u);  // 65536 blocks
    reshape_78271484002964_kernel<<<grid, block>>>(in, out);
}

// round 2
// speedup vs baseline: 1.1230x; 1.1230x over previous
#include <cuda_runtime.h>

// Permutation: x[B=16, C=64, H=256, W=256] fp32
//   out[b][i][j][k][cc][hh][ww] = x[b][i*32+cc][j*16+hh][k*16+ww]
//   (s0,s1,s2)=(2,16,16); innermost w=16 floats (64B) contiguous both sides.
//
// Round 2: 4x grid-stride unroll per thread -> 4 front-batched LDG.128 in
// flight per thread (MLP=4) to saturate DRAM queues; stores stay perfectly
// warp-coalesced. Streaming (.cs) hints since data is touched exactly once.

static constexpr unsigned TOTAL_F4 = (16u * 64u * 256u * 256u) / 4u;  // 16,777,216
static constexpr unsigned UNROLL   = 4u;
static constexpr unsigned NTHREADS = TOTAL_F4 / UNROLL;               // 4,194,304

__device__ __forceinline__ unsigned out_to_in_f4(unsigned t) {
    // Output float4 index -> input float4 index (all power-of-two fields).
    // out float idx = (((((b*2+i)*16+j)*16+k)*32+cc)*16+hh)*16+ww
    unsigned ww4 = t & 3u;
    unsigned r   = t >> 2;
    unsigned hh  = r & 15u;  r >>= 4;
    unsigned cc  = r & 31u;  r >>= 5;
    unsigned k   = r & 15u;  r >>= 4;
    unsigned j   = r & 15u;  r >>= 4;
    unsigned i   = r & 1u;
    unsigned b   = r >> 1;
    unsigned channel = (b << 6) + (i << 5) + cc;
    unsigned row     = (j << 4) + hh;
    return (channel << 14) + (row << 6) + (k << 2) + ww4;
}

__global__ __launch_bounds__(256)
void reshape_78271484002964_kernel(const float4* __restrict__ in,
                                   float4* __restrict__ out) {
    unsigned tid = blockIdx.x * blockDim.x + threadIdx.x;

    unsigned t0 = tid;
    unsigned t1 = tid + NTHREADS;
    unsigned t2 = tid + 2u * NTHREADS;
    unsigned t3 = tid + 3u * NTHREADS;

    unsigned s0 = out_to_in_f4(t0);
    unsigned s1 = out_to_in_f4(t1);
    unsigned s2 = out_to_in_f4(t2);
    unsigned s3 = out_to_in_f4(t3);

    // Front-batch all loads (MLP=4) before any store.
    float4 v0 = __ldcs(&in[s0]);
    float4 v1 = __ldcs(&in[s1]);
    float4 v2 = __ldcs(&in[s2]);
    float4 v3 = __ldcs(&in[s3]);

    __stcs(&out[t0], v0);
    __stcs(&out[t1], v1);
    __stcs(&out[t2], v2);
    __stcs(&out[t3], v3);
}

extern "C" void kernel_launch(void* const* d_in, const int* in_sizes, int n_in,
                              void* d_out, int out_size) {
    const float4* in  = (const float4*)d_in[0];
    float4*       out = (float4*)d_out;

    dim3 block(256);
    dim3 grid(NTHREADS / 256u);  // 16384 blocks
    reshape_78271484002964_kernel<<<grid, block>>>(in, out);
}

// round 3
// speedup vs baseline: 1.1243x; 1.0012x over previous
#include <cuda_runtime.h>

// Permutation: x[B=16, C=64, H=256, W=256] fp32
//   out[b][i][j][k][cc][hh][ww] = x[b][i*32+cc][j*16+hh][k*16+ww]
//   (s0,s1,s2)=(2,16,16); innermost w=16 floats (64B) contiguous both sides.
//
// Round 3: 8x unroll with stride N = TOTAL/8 = 2^21 float4.
// Output-index fields (low->high bits): ww4(2) hh(4) cc(5) k(4) j(4) i(1) b(4).
// Adding 2^21 only bumps b by 2 => input index shifts by a CONSTANT 2^21 f4.
// So: one index decomposition + 7 constant adds; 8 front-batched LDG.128
// (MLP=8); stores stay perfectly warp-coalesced output-linear.

static constexpr unsigned TOTAL_F4 = (16u * 64u * 256u * 256u) / 4u;  // 2^24
static constexpr unsigned UNROLL   = 8u;
static constexpr unsigned NTHREADS = TOTAL_F4 / UNROLL;               // 2^21
static constexpr unsigned STRIDE   = NTHREADS;                        // 2^21 (both spaces)

__global__ __launch_bounds__(256)
void reshape_78271484002964_kernel(const float4* __restrict__ in,
                                   float4* __restrict__ out) {
    unsigned t = blockIdx.x * blockDim.x + threadIdx.x;  // 0 .. 2^21-1

    // Decompose t (covers b in {0,1}; higher b reached via +STRIDE steps).
    unsigned ww4 = t & 3u;
    unsigned r   = t >> 2;
    unsigned hh  = r & 15u;  r >>= 4;
    unsigned cc  = r & 31u;  r >>= 5;
    unsigned k   = r & 15u;  r >>= 4;
    unsigned j   = r & 15u;  r >>= 4;
    unsigned i   = r & 1u;
    unsigned b   = r >> 1;   // 0 or 1

    unsigned channel = (b << 6) + (i << 5) + cc;
    unsigned row     = (j << 4) + hh;
    unsigned s       = (channel << 14) + (row << 6) + (k << 2) + ww4;

    // Front-batch all 8 loads (independent addresses, constant stride).
    float4 v0 = __ldcs(&in[s + 0u * STRIDE]);
    float4 v1 = __ldcs(&in[s + 1u * STRIDE]);
    float4 v2 = __ldcs(&in[s + 2u * STRIDE]);
    float4 v3 = __ldcs(&in[s + 3u * STRIDE]);
    float4 v4 = __ldcs(&in[s + 4u * STRIDE]);
    float4 v5 = __ldcs(&in[s + 5u * STRIDE]);
    float4 v6 = __ldcs(&in[s + 6u * STRIDE]);
    float4 v7 = __ldcs(&in[s + 7u * STRIDE]);

    __stcs(&out[t + 0u * STRIDE], v0);
    __stcs(&out[t + 1u * STRIDE], v1);
    __stcs(&out[t + 2u * STRIDE], v2);
    __stcs(&out[t + 3u * STRIDE], v3);
    __stcs(&out[t + 4u * STRIDE], v4);
    __stcs(&out[t + 5u * STRIDE], v5);
    __stcs(&out[t + 6u * STRIDE], v6);
    __stcs(&out[t + 7u * STRIDE], v7);
}

extern "C" void kernel_launch(void* const* d_in, const int* in_sizes, int n_in,
                              void* d_out, int out_size) {
    const float4* in  = (const float4*)d_in[0];
    float4*       out = (float4*)d_out;

    dim3 block(256);
    dim3 grid(NTHREADS / 256u);  // 8192 blocks
    reshape_78271484002964_kernel<<<grid, block>>>(in, out);
}

// round 4
// speedup vs baseline: 1.1304x; 1.0055x over previous
#include <cuda_runtime.h>

// Permutation: x[B=16, C=64, H=256, W=256] fp32
//   out[b][i][j][k][cc][hh][ww] = x[b][i*32+cc][j*16+hh][k*16+ww]
//
// Round 4: SMEM-tiled. Each CTA owns (b, i, j, cc):
//   input tile  = 1024 contiguous f4 (16 KB)  -> fully coalesced streaming loads
//   output tile = 16 chunks of 64 f4 (1 KB each, stride 2^11 f4) -> coalesced stores
// SMEM row padded 64 -> 68 f4 so both STS (input order) and LDS (output order)
// phases are bank-conflict-free for 128-bit accesses.

static constexpr unsigned NBLOCKS = 16u * 2u * 16u * 32u;  // (b,i,j,cc) = 16384

__global__ __launch_bounds__(256)
void reshape_78271484002964_kernel(const float4* __restrict__ in,
                                   float4* __restrict__ out) {
    __shared__ float4 sm[16 * 68];  // [hh][k*4+ww4 padded to 68] = 17408 B

    unsigned bid = blockIdx.x;
    unsigned cc = bid & 31u;
    unsigned j  = (bid >> 5) & 15u;
    unsigned i  = (bid >> 9) & 1u;
    unsigned b  = bid >> 10;

    unsigned channel = (b << 6) + (i << 5) + cc;
    const float4* src = in + (channel << 14) + (j << 10);

    unsigned t = threadIdx.x;

    // ---- Phase 1: stream 16 KB contiguous input (front-batched) ----
    float4 v0 = __ldcs(src + t);
    float4 v1 = __ldcs(src + t + 256u);
    float4 v2 = __ldcs(src + t + 512u);
    float4 v3 = __ldcs(src + t + 768u);

    // input-linear offset o: hh = o>>6, kw = o&63 ; smem addr = hh*68 + kw
    sm[((t          ) >> 6) * 68u + ((t          ) & 63u)] = v0;
    sm[((t +  256u  ) >> 6) * 68u + ((t +  256u  ) & 63u)] = v1;
    sm[((t +  512u  ) >> 6) * 68u + ((t +  512u  ) & 63u)] = v2;
    sm[((t +  768u  ) >> 6) * 68u + ((t +  768u  ) & 63u)] = v3;

    __syncthreads();

    // ---- Phase 2: emit in output order ----
    // out f4 idx = ww4 | hh<<2 | cc<<6 | k<<11 | j<<15 | i<<19 | b<<20
    unsigned out_base = (cc << 6) + (j << 15) + (i << 19) + (b << 20);

#pragma unroll
    for (unsigned it = 0; it < 4u; ++it) {
        unsigned p    = t + it * 256u;        // output-linear offset in tile
        unsigned ww4  = p & 3u;
        unsigned hh   = (p >> 2) & 15u;
        unsigned k    = p >> 6;
        float4 v = sm[hh * 68u + (k << 2) + ww4];
        __stcs(&out[out_base + (k << 11) + (p & 63u)], v);
    }
}

extern "C" void kernel_launch(void* const* d_in, const int* in_sizes, int n_in,
                              void* d_out, int out_size) {
    const float4* in  = (const float4*)d_in[0];
    float4*       out = (float4*)d_out;

    reshape_78271484002964_kernel<<<NBLOCKS, 256>>>(in, out);
}